// round 3
// baseline (speedup 1.0000x reference)
#include <cuda_runtime.h>

#define NN    20000
#define NPAD  20096   // 157 * 128
#define NE    320000

// ---------------- scratch (static device memory, no allocs) ----------------
__device__ float  g_H[(size_t)NPAD * 1024];   // current node features
__device__ float  g_A[(size_t)NPAD * 1024];   // per-node GEMM1 output (node part of hidden)
__device__ float  g_B[(size_t)NPAD * 1024];   // aggregated relu'd hidden (segment sum)
__device__ float2 g_rel[NE];                  // rel_pos per edge
__device__ float  g_cnt[NPAD];
__device__ float  g_inv[NPAD];
__device__ float  g_msk[NPAD];

__device__ __forceinline__ float* selbuf(int s) {
    return s == 0 ? g_H : (s == 1 ? g_A : g_B);
}

// ---------------- small utility kernels ----------------
__global__ void k_zero_B(long n4) {  // zero first n4 float4s of g_B
    long i = (long)blockIdx.x * blockDim.x + threadIdx.x;
    long stride = (long)gridDim.x * blockDim.x;
    float4 z = make_float4(0.f, 0.f, 0.f, 0.f);
    float4* p = (float4*)g_B;
    for (; i < n4; i += stride) p[i] = z;
}

__global__ void k_zero_cnt() {
    int i = blockIdx.x * blockDim.x + threadIdx.x;
    if (i < NPAD) g_cnt[i] = 0.f;
}

__global__ void k_copy_h(const float* __restrict__ src) {
    int i = blockIdx.x * blockDim.x + threadIdx.x;   // over NPAD*16/4
    if (i < NPAD * 16 / 4) {
        float4 v = (i < NN * 16 / 4) ? ((const float4*)src)[i] : make_float4(0.f, 0.f, 0.f, 0.f);
        ((float4*)g_H)[i] = v;
    }
}

// edge_index is int32 [2, NE] (JAX default x64-disabled downgrades int64)
__global__ void k_prep(const int* __restrict__ ei, const float* __restrict__ pos) {
    int e = blockIdx.x * blockDim.x + threadIdx.x;
    if (e < NE) {
        int s = ei[e];
        int d = ei[NE + e];
        float2 ps = ((const float2*)pos)[s];
        float2 pd = ((const float2*)pos)[d];
        g_rel[e] = make_float2(ps.x - pd.x, ps.y - pd.y);
        atomicAdd(g_cnt + d, 1.0f);
    }
}

__global__ void k_fin() {
    int i = blockIdx.x * blockDim.x + threadIdx.x;
    if (i < NPAD) {
        float c = g_cnt[i];
        g_inv[i] = 1.0f / fmaxf(c, 1.0f);
        g_msk[i] = (c > 0.0f) ? 1.0f : 0.0f;
    }
}

// ---------------- SGEMM: C[M=NPAD, N] = A[M,K] @ B[K,N] (+epilogue) ----------------
// row-major A (stride K), row-major B (stride N). Requires K%16==0, N%128==0.
template <bool RELU, bool SCALED>
__global__ __launch_bounds__(256) void sgemm_kernel(
    int K, int N, int srcSel, int dstSel,
    const float* __restrict__ B, const float* __restrict__ bias)
{
    constexpr int BM = 128, BN = 128, BK = 16, TM = 8, TN = 8;
    __shared__ __align__(16) float As[BK][BM];
    __shared__ __align__(16) float Bs[BK][BN];

    const float* A = selbuf(srcSel);
    float*       C = selbuf(dstSel);

    const int bm = blockIdx.y * BM;
    const int bn = blockIdx.x * BN;
    const int tid = threadIdx.x;

    const int arow = tid >> 2;          // 0..63
    const int acol = (tid & 3) << 2;    // 0,4,8,12
    const int brow = tid >> 5;          // 0..7
    const int bcol = (tid & 31) << 2;   // 0..124

    const int ty = (tid >> 4) * TM;
    const int tx = (tid & 15) * TN;

    float acc[TM][TN];
#pragma unroll
    for (int i = 0; i < TM; i++)
#pragma unroll
        for (int j = 0; j < TN; j++) acc[i][j] = 0.f;

    const float* Aptr = A + (long)bm * K;
    const float* Bptr = B + bn;

    for (int k0 = 0; k0 < K; k0 += BK) {
#pragma unroll
        for (int i = 0; i < 2; i++) {
            int r = arow + i * 64;
            float4 v = *(const float4*)(Aptr + (long)r * K + k0 + acol);
            As[acol + 0][r] = v.x;
            As[acol + 1][r] = v.y;
            As[acol + 2][r] = v.z;
            As[acol + 3][r] = v.w;
        }
#pragma unroll
        for (int i = 0; i < 2; i++) {
            int r = brow + i * 8;
            *(float4*)(&Bs[r][bcol]) = *(const float4*)(Bptr + (long)(k0 + r) * N + bcol);
        }
        __syncthreads();

#pragma unroll
        for (int kk = 0; kk < BK; kk++) {
            float ra[TM], rb[TN];
            *(float4*)(ra)     = *(const float4*)(&As[kk][ty]);
            *(float4*)(ra + 4) = *(const float4*)(&As[kk][ty + 4]);
            *(float4*)(rb)     = *(const float4*)(&Bs[kk][tx]);
            *(float4*)(rb + 4) = *(const float4*)(&Bs[kk][tx + 4]);
#pragma unroll
            for (int i = 0; i < TM; i++)
#pragma unroll
                for (int j = 0; j < TN; j++) acc[i][j] += ra[i] * rb[j];
        }
        __syncthreads();
    }

#pragma unroll
    for (int i = 0; i < TM; i++) {
        long m = bm + ty + i;
        float scale = SCALED ? g_inv[m] : 1.0f;
        float bmsk  = SCALED ? g_msk[m] : 1.0f;
        float* crow = C + m * N + bn + tx;
#pragma unroll
        for (int j = 0; j < TN; j += 4) {
            float4 bv = *(const float4*)(bias + bn + tx + j);
            float4 o;
            o.x = acc[i][j + 0] * scale + bv.x * bmsk;
            o.y = acc[i][j + 1] * scale + bv.y * bmsk;
            o.z = acc[i][j + 2] * scale + bv.z * bmsk;
            o.w = acc[i][j + 3] * scale + bv.w * bmsk;
            if (RELU) {
                o.x = fmaxf(o.x, 0.f); o.y = fmaxf(o.y, 0.f);
                o.z = fmaxf(o.z, 0.f); o.w = fmaxf(o.w, 0.f);
            }
            *(float4*)(crow + j) = o;
        }
    }
}

// ---------------- per-edge gather + relu + scatter-add ----------------
// z = relu(g_A[src] + rx*w1p[0,:] + ry*w1p[1,:]); g_B[dst] += z
// TPE threads cooperate on one edge, H == TPE*4.
template <int H, int TPE, int ITERS>
__global__ __launch_bounds__(256) void edge_kernel(
    const int* __restrict__ ei,
    const float* __restrict__ w1p)  // last-2-rows of w1: [2*H]
{
    static_assert(H == TPE * 4, "one float4 per thread");
    __shared__ __align__(16) float sw0[H];
    __shared__ __align__(16) float sw1[H];
    for (int i = threadIdx.x; i < H; i += 256) {
        sw0[i] = w1p[i];
        sw1[i] = w1p[H + i];
    }
    __syncthreads();

    constexpr int EPB = 256 / TPE;
    const int lane = threadIdx.x & (TPE - 1);
    const int sub  = threadIdx.x / TPE;
    const int v    = lane * 4;

    const float4 w0 = *(const float4*)(sw0 + v);
    const float4 w1 = *(const float4*)(sw1 + v);

    long base = (long)blockIdx.x * EPB * ITERS;
#pragma unroll 1
    for (int it = 0; it < ITERS; it++) {
        long e = base + (long)it * EPB + sub;
        if (e >= NE) return;
        int src = ei[e];
        int dst = ei[NE + e];
        float2 rp = g_rel[e];
        float4 a = *(const float4*)(g_A + (long)src * H + v);
        float4 z;
        z.x = fmaxf(fmaf(rp.x, w0.x, fmaf(rp.y, w1.x, a.x)), 0.f);
        z.y = fmaxf(fmaf(rp.x, w0.y, fmaf(rp.y, w1.y, a.y)), 0.f);
        z.z = fmaxf(fmaf(rp.x, w0.z, fmaf(rp.y, w1.z, a.z)), 0.f);
        z.w = fmaxf(fmaf(rp.x, w0.w, fmaf(rp.y, w1.w, a.w)), 0.f);
        float* out = g_B + (long)dst * H + v;
        atomicAdd(out + 0, z.x);
        atomicAdd(out + 1, z.y);
        atomicAdd(out + 2, z.z);
        atomicAdd(out + 3, z.w);
    }
}

// ---------------- head final: out[M,4] = g_B[M,512] @ W[512,4] + b ----------------
__global__ void k_head_final(const float* __restrict__ W,
                             const float* __restrict__ b, float* __restrict__ out) {
    int warp = (blockIdx.x * blockDim.x + threadIdx.x) >> 5;
    int lane = threadIdx.x & 31;
    if (warp >= NN) return;
    const float* x = g_B + (long)warp * 512;
    float a0 = 0.f, a1 = 0.f, a2 = 0.f, a3 = 0.f;
    for (int k = lane; k < 512; k += 32) {
        float xv = x[k];
        float4 w = *(const float4*)(W + k * 4);
        a0 = fmaf(xv, w.x, a0);
        a1 = fmaf(xv, w.y, a1);
        a2 = fmaf(xv, w.z, a2);
        a3 = fmaf(xv, w.w, a3);
    }
#pragma unroll
    for (int off = 16; off > 0; off >>= 1) {
        a0 += __shfl_down_sync(0xffffffffu, a0, off);
        a1 += __shfl_down_sync(0xffffffffu, a1, off);
        a2 += __shfl_down_sync(0xffffffffu, a2, off);
        a3 += __shfl_down_sync(0xffffffffu, a3, off);
    }
    if (lane == 0) {
        float4 bb = *(const float4*)b;
        float4 o = make_float4(a0 + bb.x, a1 + bb.y, a2 + bb.z, a3 + bb.w);
        ((float4*)out)[warp] = o;
    }
}

// ---------------- host orchestration ----------------
static void launch_gemm(int K, int N, int srcSel, int dstSel,
                        const float* B, const float* bias, bool scaled, bool relu) {
    dim3 grid(N / 128, NPAD / 128);
    if (relu) {
        if (scaled) sgemm_kernel<true, true><<<grid, 256>>>(K, N, srcSel, dstSel, B, bias);
        else        sgemm_kernel<true, false><<<grid, 256>>>(K, N, srcSel, dstSel, B, bias);
    } else {
        if (scaled) sgemm_kernel<false, true><<<grid, 256>>>(K, N, srcSel, dstSel, B, bias);
        else        sgemm_kernel<false, false><<<grid, 256>>>(K, N, srcSel, dstSel, B, bias);
    }
}

extern "C" void kernel_launch(void* const* d_in, const int* in_sizes, int n_in,
                              void* d_out, int out_size) {
    const float* h_in = (const float*)d_in[0];
    const float* pos  = (const float*)d_in[1];
    const int*   ei   = (const int*)d_in[2];   // int32 [2, NE]
    const float* l1_w1 = (const float*)d_in[3];
    const float* l1_b1 = (const float*)d_in[4];
    const float* l1_w2 = (const float*)d_in[5];
    const float* l1_b2 = (const float*)d_in[6];
    const float* l2_w1 = (const float*)d_in[7];
    const float* l2_b1 = (const float*)d_in[8];
    const float* l2_w2 = (const float*)d_in[9];
    const float* l2_b2 = (const float*)d_in[10];
    const float* l3_w1 = (const float*)d_in[11];
    const float* l3_b1 = (const float*)d_in[12];
    const float* l3_w2 = (const float*)d_in[13];
    const float* l3_b2 = (const float*)d_in[14];
    const float* l4_w1 = (const float*)d_in[15];
    const float* l4_b1 = (const float*)d_in[16];
    const float* l4_w2 = (const float*)d_in[17];
    const float* l4_b2 = (const float*)d_in[18];
    const float* hd_w1 = (const float*)d_in[19];
    const float* hd_b1 = (const float*)d_in[20];
    const float* hd_w2 = (const float*)d_in[21];
    const float* hd_b2 = (const float*)d_in[22];
    const float* hd_w3 = (const float*)d_in[23];
    const float* hd_b3 = (const float*)d_in[24];

    // --- prep: counts, inv/mask, rel_pos, padded h ---
    k_zero_cnt<<<(NPAD + 255) / 256, 256>>>();
    k_prep<<<(NE + 255) / 256, 256>>>(ei, pos);
    k_fin<<<(NPAD + 255) / 256, 256>>>();
    k_copy_h<<<(NPAD * 16 / 4 + 255) / 256, 256>>>(h_in);

    // --- layer 1: 16 -> 128 -> 128 ---  (buffers: 0=g_H, 1=g_A, 2=g_B)
    launch_gemm(16, 128, 0, 1, l1_w1, l1_b1, false, false);
    k_zero_B<<<2048, 256>>>((long)NPAD * 128 / 4);
    edge_kernel<128, 32, 4><<<(NE + 31) / 32, 256>>>(ei, l1_w1 + 16 * 128);
    launch_gemm(128, 128, 2, 0, l1_w2, l1_b2, true, true);

    // --- layer 2: 128 -> 256 -> 256 ---
    launch_gemm(128, 256, 0, 1, l2_w1, l2_b1, false, false);
    k_zero_B<<<2048, 256>>>((long)NPAD * 256 / 4);
    edge_kernel<256, 64, 4><<<(NE + 15) / 16, 256>>>(ei, l2_w1 + 128 * 256);
    launch_gemm(256, 256, 2, 0, l2_w2, l2_b2, true, true);

    // --- layer 3: 256 -> 1024 -> 1024 ---
    launch_gemm(256, 1024, 0, 1, l3_w1, l3_b1, false, false);
    k_zero_B<<<4096, 256>>>((long)NPAD * 1024 / 4);
    edge_kernel<1024, 256, 16><<<(NE + 15) / 16, 256>>>(ei, l3_w1 + 256 * 1024);
    launch_gemm(1024, 1024, 2, 0, l3_w2, l3_b2, true, true);

    // --- layer 4: 1024 -> 1024 -> 1024 ---
    launch_gemm(1024, 1024, 0, 1, l4_w1, l4_b1, false, false);
    k_zero_B<<<4096, 256>>>((long)NPAD * 1024 / 4);
    edge_kernel<1024, 256, 16><<<(NE + 15) / 16, 256>>>(ei, l4_w1 + 1024 * 1024);
    launch_gemm(1024, 1024, 2, 0, l4_w2, l4_b2, true, true);

    // --- head: 1024 -> 1024 -> 512 -> 4 ---
    launch_gemm(1024, 1024, 0, 1, hd_w1, hd_b1, false, true);
    launch_gemm(1024, 512, 1, 2, hd_w2, hd_b2, false, true);
    k_head_final<<<(NN * 32 + 255) / 256, 256>>>(hd_w3, hd_b3, (float*)d_out);
}